// round 14
// baseline (speedup 1.0000x reference)
#include <cuda_runtime.h>
#include <cuda_fp16.h>
#include <cstdint>

#define DI __device__ __forceinline__

namespace {
constexpr int Bb = 8192, INN = 2048, HH = 2048, KG = 4096;
constexpr int BM = 128, BN = 128, BK = 64;
constexpr int NTH = 256;                      // 8 warps: 2 (M) x 4 (N), 64x32 warp tile
constexpr int OFF_WG = 16384, OFF_WI = 32768; // A 16KB | Wg 16KB | Wi 16KB
constexpr int STG_BYTES = 48 * 1024;
constexpr int NSTAGE = 4;
constexpr int SMEM_TOTAL = NSTAGE * STG_BYTES;  // 192KB, occ 1

constexpr int NCH  = KG / BK;    // 64 chunks total (gate)
constexpr int NCHV = INN / BK;   // 32 chunks also feed values
constexpr int NXT = HH / BN;     // 16 tiles along N

constexpr float WSCALE = 4096.0f;
constexpr float INV_WSCALE = 1.0f / 4096.0f;
}

// fp16 scratch
__device__ __align__(1024) __half g_CAh[(size_t)Bb * KG];
__device__ __align__(1024) __half g_Wgh[(size_t)HH * KG];
__device__ __align__(1024) __half g_Wih[(size_t)HH * INN];

// ---------------- PTX helpers ----------------
DI uint32_t smem_u32(const void* p) {
    uint32_t a;
    asm("{ .reg .u64 t; cvta.to.shared.u64 t, %1; cvt.u32.u64 %0, t; }" : "=r"(a) : "l"(p));
    return a;
}
DI void cp16(uint32_t s, const void* g) {
    asm volatile("cp.async.cg.shared.global [%0], [%1], 16;" :: "r"(s), "l"(g) : "memory");
}
DI void cp_commit() { asm volatile("cp.async.commit_group;" ::: "memory"); }
template <int N>
DI void cp_wait() { asm volatile("cp.async.wait_group %0;" :: "n"(N) : "memory"); }

DI void ldsm_x4(uint32_t* r, uint32_t addr) {
    asm volatile("ldmatrix.sync.aligned.m8n8.x4.shared.b16 {%0,%1,%2,%3}, [%4];"
                 : "=r"(r[0]), "=r"(r[1]), "=r"(r[2]), "=r"(r[3]) : "r"(addr));
}
DI void mma_f16(float* d, const uint32_t* a, const uint32_t* b) {
    asm volatile(
        "mma.sync.aligned.m16n8k16.row.col.f32.f16.f16.f32 "
        "{%0,%1,%2,%3}, {%4,%5,%6,%7}, {%8,%9}, {%0,%1,%2,%3};"
        : "+f"(d[0]), "+f"(d[1]), "+f"(d[2]), "+f"(d[3])
        : "r"(a[0]), "r"(a[1]), "r"(a[2]), "r"(a[3]), "r"(b[0]), "r"(b[1]));
}

DI uint32_t swz(int row, int c16) {
    return (uint32_t)(row * 128 + ((c16 ^ (row & 7)) << 4));
}

// ---------------- merged conversion kernel ----------------
__global__ __launch_bounds__(256) void convert_all(
    const float4* __restrict__ in4, const float4* __restrict__ st4,
    float4* __restrict__ concat4,
    const float4* __restrict__ wg4, const float4* __restrict__ wi4)
{
    const int bid = blockIdx.x, t = threadIdx.x;

    if (bid < 16384) {                       // ---- A convert + concat
        int idx = bid * 256 + t;             // Bb*512
        int row = idx >> 9, c4 = idx & 511;

        float4 vi = in4[(size_t)row * 512 + c4];
        concat4[(size_t)row * 1024 + c4] = vi;
        size_t off = (size_t)row * KG + (size_t)c4 * 4;
        {
            __half2* h = (__half2*)(g_CAh + off);
            h[0] = __floats2half2_rn(vi.x, vi.y);
            h[1] = __floats2half2_rn(vi.z, vi.w);
        }
        float4 vs = st4[(size_t)row * 512 + c4];
        concat4[(size_t)row * 1024 + 512 + c4] = vs;
        off += INN;
        {
            __half2* h = (__half2*)(g_CAh + off);
            h[0] = __floats2half2_rn(vs.x, vs.y);
            h[1] = __floats2half2_rn(vs.z, vs.w);
        }
    } else if (bid < 16384 + 8192) {         // ---- Wg convert
        int idx = (bid - 16384) * 256 + t;
        float4 v = wg4[idx];
        __half2* ph = (__half2*)(g_Wgh + (size_t)idx * 4);
        ph[0] = __floats2half2_rn(v.x * WSCALE, v.y * WSCALE);
        ph[1] = __floats2half2_rn(v.z * WSCALE, v.w * WSCALE);
    } else {                                  // ---- Wi convert
        int idx = (bid - 24576) * 256 + t;
        float4 v = wi4[idx];
        __half2* ph = (__half2*)(g_Wih + (size_t)idx * 4);
        ph[0] = __floats2half2_rn(v.x * WSCALE, v.y * WSCALE);
        ph[1] = __floats2half2_rn(v.z * WSCALE, v.w * WSCALE);
    }
}

// ---------------- bulk stage load (prologue) ----------------
DI void load_stage(uint32_t st, const __half* Ah, const __half* Wg, const __half* Wi,
                   int bm, int bn, int kc, int t)
{
    const int r = t >> 1, c0 = (t & 1) * 4;
    const char* pA = (const char*)(Ah + (size_t)(bm + r) * KG + kc);
    const char* pG = (const char*)(Wg + (size_t)(bn + r) * KG + kc);
    #pragma unroll
    for (int j = 0; j < 4; j++) {
        const uint32_t so = swz(r, c0 + j);
        cp16(st + so,          pA + (c0 + j) * 16);
        cp16(st + OFF_WG + so, pG + (c0 + j) * 16);
    }
    if (kc < INN) {
        const char* pI = (const char*)(Wi + (size_t)(bn + r) * INN + kc);
        #pragma unroll
        for (int j = 0; j < 4; j++)
            cp16(st + OFF_WI + swz(r, c0 + j), pI + (c0 + j) * 16);
    }
}

// ---------------- fused tile kernel: both GEMMs per (bm,bn) ----------------
__global__ __launch_bounds__(NTH, 1)
void gemm_fused(const __half* __restrict__ Ah,
                const __half* __restrict__ Wg, const __half* __restrict__ Wi,
                const float* __restrict__ state, const float* __restrict__ bias,
                float* __restrict__ values_o, float* __restrict__ pre_gate_o,
                float* __restrict__ gate_o, float* __restrict__ pre_h_o,
                float* __restrict__ new_h_o)
{
    extern __shared__ char smem[];
    const uint32_t sb = smem_u32(smem);
    const int bid = blockIdx.x;
    const int bm = (bid / NXT) * BM, bn = (bid % NXT) * BN;

    const int t = threadIdx.x, wid = t >> 5, lane = t & 31;
    const int warp_m = wid >> 2, warp_n = wid & 3;   // 2 x 4

    float acc_g[4][4][4] = {};   // gate accumulator (64 regs)
    float acc_v[4][4][4] = {};   // values accumulator (64 regs)

    load_stage(sb,                 Ah, Wg, Wi, bm, bn, 0,      t); cp_commit();
    load_stage(sb + STG_BYTES,     Ah, Wg, Wi, bm, bn, BK,     t); cp_commit();
    load_stage(sb + 2 * STG_BYTES, Ah, Wg, Wi, bm, bn, 2 * BK, t); cp_commit();

    const int a_row = warp_m * 64 + (lane & 15);
    const int a_chi = lane >> 4;
    const int lm = lane >> 3;
    const int b_row = warp_n * 32 + (lane & 7) + ((lm >> 1) << 3);
    const int b_chi = lm & 1;

    const int ra = t >> 1, ca = (t & 1) * 4;

    uint32_t af[2][4][4];         // double-buffered A fragments
    uint32_t bg[2][4], bv[2][4];  // single-buffered W fragments

    cp_wait<2>();
    __syncthreads();
    #pragma unroll
    for (int mt = 0; mt < 4; mt++)
        ldsm_x4(af[0][mt], sb + swz(a_row + mt * 16, a_chi));

    for (int k = 0; k < NCH; k++) {
        const uint32_t st  = sb + (k & 3) * STG_BYTES;
        const uint32_t st3 = sb + ((k + 3) & 3) * STG_BYTES;
        const uint32_t stn = sb + ((k + 1) & 3) * STG_BYTES;
        const int kc3 = (k + 3) * BK;
        const bool do_load = (k + 3 < NCH);
        const bool load_wi = (k + 3 < NCHV);
        const bool dual    = (k < NCHV);
        const bool more    = (k + 1 < NCH);

        const char* pA3 = (const char*)(Ah + (size_t)(bm + ra) * KG + kc3);
        const char* pG3 = (const char*)(Wg + (size_t)(bn + ra) * KG + kc3);
        const char* pI3 = (const char*)(Wi + (size_t)(bn + ra) * INN + kc3);

        #pragma unroll
        for (int s = 0; s < 4; s++) {
            const int cur = s & 1, nxt = cur ^ 1;
            const int c0 = 2 * s;

            // W fragments for this step
            #pragma unroll
            for (int np = 0; np < 2; np++)
                ldsm_x4(bg[np], st + OFF_WG + swz(b_row + np * 16, c0 + b_chi));
            if (dual) {
                #pragma unroll
                for (int np = 0; np < 2; np++)
                    ldsm_x4(bv[np], st + OFF_WI + swz(b_row + np * 16, c0 + b_chi));
            }

            // interleaved global->smem for chunk k+3
            if (do_load) {
                if (s == 0) {
                    cp16(st3 + swz(ra, ca + 0), pA3 + (ca + 0) * 16);
                    cp16(st3 + swz(ra, ca + 1), pA3 + (ca + 1) * 16);
                    cp16(st3 + OFF_WG + swz(ra, ca + 0), pG3 + (ca + 0) * 16);
                } else if (s == 1) {
                    cp16(st3 + swz(ra, ca + 2), pA3 + (ca + 2) * 16);
                    cp16(st3 + swz(ra, ca + 3), pA3 + (ca + 3) * 16);
                    cp16(st3 + OFF_WG + swz(ra, ca + 1), pG3 + (ca + 1) * 16);
                } else if (s == 2) {
                    cp16(st3 + OFF_WG + swz(ra, ca + 2), pG3 + (ca + 2) * 16);
                    cp16(st3 + OFF_WG + swz(ra, ca + 3), pG3 + (ca + 3) * 16);
                    if (load_wi)
                        cp16(st3 + OFF_WI + swz(ra, ca + 0), pI3 + (ca + 0) * 16);
                } else if (load_wi) {
                    cp16(st3 + OFF_WI + swz(ra, ca + 1), pI3 + (ca + 1) * 16);
                    cp16(st3 + OFF_WI + swz(ra, ca + 2), pI3 + (ca + 2) * 16);
                    cp16(st3 + OFF_WI + swz(ra, ca + 3), pI3 + (ca + 3) * 16);
                }
            }

            // A fragment prefetch (double buffer)
            if (s < 3) {
                #pragma unroll
                for (int mt = 0; mt < 4; mt++)
                    ldsm_x4(af[nxt][mt], st + swz(a_row + mt * 16, 2 * (s + 1) + a_chi));
            } else if (more) {
                #pragma unroll
                for (int mt = 0; mt < 4; mt++)
                    ldsm_x4(af[nxt][mt], stn + swz(a_row + mt * 16, a_chi));
            }

            #pragma unroll
            for (int mt = 0; mt < 4; mt++)
                #pragma unroll
                for (int nt = 0; nt < 4; nt++)
                    mma_f16(acc_g[mt][nt], af[cur][mt], bg[nt >> 1] + (nt & 1) * 2);
            if (dual) {
                #pragma unroll
                for (int mt = 0; mt < 4; mt++)
                    #pragma unroll
                    for (int nt = 0; nt < 4; nt++)
                        mma_f16(acc_v[mt][nt], af[cur][mt], bv[nt >> 1] + (nt & 1) * 2);
            }

            if (s == 2 && more) {
                cp_wait<1>();      // stage k+1 fully arrived
                __syncthreads();
            }
        }
        cp_commit();
    }

    // fused epilogue: all five [B,H] outputs from registers
    const int er = bm + warp_m * 64 + (lane >> 2);
    const int ec = bn + warp_n * 32 + (lane & 3) * 2;

    #pragma unroll
    for (int mt = 0; mt < 4; mt++) {
        #pragma unroll
        for (int half = 0; half < 2; half++) {
            const size_t row = (size_t)(er + mt * 16 + half * 8) * HH;
            #pragma unroll
            for (int nt = 0; nt < 4; nt++) {
                const int n = ec + nt * 8;
                const float* ag = &acc_g[mt][nt][half * 2];
                const float* av = &acc_v[mt][nt][half * 2];
                float2 bi = *(const float2*)(&bias[n]);
                float2 sv = *(const float2*)(&state[row + n]);
                float2 vv = { tanhf(av[0] * INV_WSCALE), tanhf(av[1] * INV_WSCALE) };
                float2 pg = { ag[0] * INV_WSCALE + bi.x, ag[1] * INV_WSCALE + bi.y };
                float2 g  = { fminf(fmaxf(pg.x, 0.f), 1.f), fminf(fmaxf(pg.y, 0.f), 1.f) };
                float2 ph = { sv.x * (1.f - g.x) + vv.x * g.x,
                              sv.y * (1.f - g.y) + vv.y * g.y };
                float2 nh = { fmaxf(ph.x, 0.f), fmaxf(ph.y, 0.f) };
                *(float2*)(&values_o[row + n])   = vv;
                *(float2*)(&pre_gate_o[row + n]) = pg;
                *(float2*)(&gate_o[row + n])     = g;
                *(float2*)(&pre_h_o[row + n])    = ph;
                *(float2*)(&new_h_o[row + n])    = nh;
            }
        }
    }
}

// ---------------- launch ----------------
extern "C" void kernel_launch(void* const* d_in, const int* in_sizes, int n_in,
                              void* d_out, int out_size) {
    const float* input  = (const float*)d_in[0];
    const float* state  = (const float*)d_in[1];
    const float* gate_w = (const float*)d_in[2];
    const float* gate_b = (const float*)d_in[3];
    const float* w_i    = (const float*)d_in[4];

    float* out = (float*)d_out;
    float* new_h    = out;
    float* concat   = new_h + (size_t)Bb * HH;
    float* pre_gate = concat + (size_t)Bb * KG;
    float* gate     = pre_gate + (size_t)Bb * HH;
    float* values   = gate + (size_t)Bb * HH;
    float* pre_h    = values + (size_t)Bb * HH;

    void *cah, *wgh, *wih;
    cudaGetSymbolAddress(&cah, g_CAh);
    cudaGetSymbolAddress(&wgh, g_Wgh);
    cudaGetSymbolAddress(&wih, g_Wih);

    cudaFuncSetAttribute(gemm_fused, cudaFuncAttributeMaxDynamicSharedMemorySize, SMEM_TOTAL);

    convert_all<<<16384 + 8192 + 4096, 256>>>(
        (const float4*)input, (const float4*)state, (float4*)concat,
        (const float4*)gate_w, (const float4*)w_i);

    gemm_fused<<<(Bb / BM) * NXT, NTH, SMEM_TOTAL>>>(
        (const __half*)cah, (const __half*)wgh, (const __half*)wih,
        state, gate_b, values, pre_gate, gate, pre_h, new_h);
}

// round 15
// speedup vs baseline: 1.0845x; 1.0845x over previous
#include <cuda_runtime.h>
#include <cuda_fp16.h>
#include <cstdint>

#define DI __device__ __forceinline__

namespace {
constexpr int Bb = 8192, INN = 2048, HH = 2048, KG = 4096;
constexpr int BM = 128, BN = 128, BK = 128;       // K-chunk = two 64-col panels
constexpr int NTH = 256;                          // 8 warps: 2 (M) x 4 (N)
constexpr int OFF_AP1 = 16384, OFF_W = 32768, OFF_WP1 = 49152;
constexpr int STG_BYTES = 64 * 1024;
constexpr int NSTAGE = 3;
constexpr int SMEM_TOTAL = NSTAGE * STG_BYTES;    // 192KB, 1 CTA/SM

constexpr float WSCALE = 4096.0f;
constexpr float INV_WSCALE = 1.0f / 4096.0f;
}

// fp16 scratch
__device__ __align__(1024) __half g_CAh[(size_t)Bb * KG];
__device__ __align__(1024) __half g_Wgh[(size_t)HH * KG];
__device__ __align__(1024) __half g_Wih[(size_t)HH * INN];

// ---------------- PTX helpers ----------------
DI uint32_t smem_u32(const void* p) {
    uint32_t a;
    asm("{ .reg .u64 t; cvta.to.shared.u64 t, %1; cvt.u32.u64 %0, t; }" : "=r"(a) : "l"(p));
    return a;
}
DI void cp16(uint32_t s, const void* g) {
    asm volatile("cp.async.cg.shared.global [%0], [%1], 16;" :: "r"(s), "l"(g) : "memory");
}
DI void cp_commit() { asm volatile("cp.async.commit_group;" ::: "memory"); }
template <int N>
DI void cp_wait() { asm volatile("cp.async.wait_group %0;" :: "n"(N) : "memory"); }

DI void ldsm_x4(uint32_t* r, uint32_t addr) {
    asm volatile("ldmatrix.sync.aligned.m8n8.x4.shared.b16 {%0,%1,%2,%3}, [%4];"
                 : "=r"(r[0]), "=r"(r[1]), "=r"(r[2]), "=r"(r[3]) : "r"(addr));
}
DI void mma_f16(float* d, const uint32_t* a, const uint32_t* b) {
    asm volatile(
        "mma.sync.aligned.m16n8k16.row.col.f32.f16.f16.f32 "
        "{%0,%1,%2,%3}, {%4,%5,%6,%7}, {%8,%9}, {%0,%1,%2,%3};"
        : "+f"(d[0]), "+f"(d[1]), "+f"(d[2]), "+f"(d[3])
        : "r"(a[0]), "r"(a[1]), "r"(a[2]), "r"(a[3]), "r"(b[0]), "r"(b[1]));
}

DI uint32_t swz(int row, int c16) {
    return (uint32_t)(row * 128 + ((c16 ^ (row & 7)) << 4));
}

// ---------------- merged conversion kernel (A + concat + Wi only) ----------------
__global__ __launch_bounds__(256) void convert_all(
    const float4* __restrict__ in4, const float4* __restrict__ st4,
    float4* __restrict__ concat4, const float4* __restrict__ wi4)
{
    const int bid = blockIdx.x, t = threadIdx.x;

    if (bid < 16384) {                       // ---- A convert + concat
        int idx = bid * 256 + t;             // Bb*512
        int row = idx >> 9, c4 = idx & 511;

        float4 vi = in4[(size_t)row * 512 + c4];
        concat4[(size_t)row * 1024 + c4] = vi;
        size_t off = (size_t)row * KG + (size_t)c4 * 4;
        {
            __half2* h = (__half2*)(g_CAh + off);
            h[0] = __floats2half2_rn(vi.x, vi.y);
            h[1] = __floats2half2_rn(vi.z, vi.w);
        }
        float4 vs = st4[(size_t)row * 512 + c4];
        concat4[(size_t)row * 1024 + 512 + c4] = vs;
        off += INN;
        {
            __half2* h = (__half2*)(g_CAh + off);
            h[0] = __floats2half2_rn(vs.x, vs.y);
            h[1] = __floats2half2_rn(vs.z, vs.w);
        }
    } else {                                  // ---- Wi convert (HH*INN/4 = 1M float4)
        int idx = (bid - 16384) * 256 + t;
        float4 v = wi4[idx];
        __half2* ph = (__half2*)(g_Wih + (size_t)idx * 4);
        ph[0] = __floats2half2_rn(v.x * WSCALE, v.y * WSCALE);
        ph[1] = __floats2half2_rn(v.z * WSCALE, v.w * WSCALE);
    }
}

// ---------------- GEMM via mma.sync (round-9 body) ----------------
DI void load_stage(uint32_t st,
                   const __half* __restrict__ Ah, const __half* __restrict__ Wh,
                   int lda, int ldw, int bm, int bn, int kc, int t)
{
    const int r0 = t >> 2, cc = t & 3;
    #pragma unroll
    for (int j = 0; j < 2; j++) {
        const int r = r0 + 64 * j;
        const char* pA = (const char*)(Ah + (size_t)(bm + r) * lda + kc);
        const char* pW = (const char*)(Wh + (size_t)(bn + r) * ldw + kc);
        #pragma unroll
        for (int i = 0; i < 2; i++) {
            const int c16 = cc + 4 * i;
            const uint32_t so = swz(r, c16);
            cp16(st + so,           pA + c16 * 16);
            cp16(st + OFF_AP1 + so, pA + 128 + c16 * 16);
            cp16(st + OFF_W + so,   pW + c16 * 16);
            cp16(st + OFF_WP1 + so, pW + 128 + c16 * 16);
        }
    }
}

template <bool GATE>
__global__ __launch_bounds__(NTH, 1)
void gemm_mma(const __half* __restrict__ Ah, const __half* __restrict__ Wh,
              int kdim,
              const float* __restrict__ state, const float* __restrict__ bias,
              const float* __restrict__ values_in,
              float* __restrict__ out0,
              float* __restrict__ gate_o, float* __restrict__ pre_h_o,
              float* __restrict__ new_h_o,
              const float4* __restrict__ wgsrc,   // ride-along Wg convert (values only)
              __half2* __restrict__ wgdst)
{
    extern __shared__ char smem[];
    const uint32_t sb = smem_u32(smem);
    const int t = threadIdx.x, wid = t >> 5, lane = t & 31;
    const int warp_m = wid >> 2, warp_n = wid & 3;      // 2 x 4
    const int bm = blockIdx.y * BM, bn = blockIdx.x * BN;
    const int r0 = t >> 2, cc = t & 3;

    float acc[4][4][4] = {};

    const int nch = kdim / BK;

    load_stage(sb, Ah, Wh, KG, kdim, bm, bn, 0, t);
    cp_commit();
    load_stage(sb + STG_BYTES, Ah, Wh, KG, kdim, bm, bn, BK, t);
    cp_commit();

    const int a_row = warp_m * 64 + (lane & 15);
    const int a_chi = lane >> 4;
    const int lm = lane >> 3;
    const int b_row = warp_n * 32 + (lane & 7) + ((lm >> 1) << 3);
    const int b_chi = lm & 1;

    uint32_t af[2][4][4], bf[2][2][4];

    cp_wait<1>();
    __syncthreads();
    #pragma unroll
    for (int mt = 0; mt < 4; mt++)
        ldsm_x4(af[0][mt], sb + swz(a_row + mt * 16, a_chi));
    #pragma unroll
    for (int np = 0; np < 2; np++)
        ldsm_x4(bf[0][np], sb + OFF_W + swz(b_row + np * 16, b_chi));

    for (int k = 0; k < nch; k++) {
        const uint32_t st  = sb + (k % NSTAGE) * STG_BYTES;           // read
        const uint32_t st2 = sb + ((k + 2) % NSTAGE) * STG_BYTES;     // write
        const int kc2 = (k + 2) * BK;
        const bool do_load = (k + 2 < nch);
        const bool more    = (k + 1 < nch);
        const uint32_t stn = sb + ((k + 1) % NSTAGE) * STG_BYTES;

        #pragma unroll
        for (int s = 0; s < 8; s++) {
            const int cur = s & 1, nxt = cur ^ 1;

            // interleaved global->smem for chunk k+2 (2 cp16 per s-step)
            if (do_load) {
                const int arr = s >> 1;      // 0:Ap0 1:Ap1 2:Wp0 3:Wp1
                const int j   = s & 1;
                const int r   = r0 + 64 * j;
                const char* gp;
                uint32_t soff;
                if (arr < 2) {
                    gp = (const char*)(Ah + (size_t)(bm + r) * KG + kc2) + (arr & 1) * 128;
                    soff = (arr & 1) ? OFF_AP1 : 0u;
                } else {
                    gp = (const char*)(Wh + (size_t)(bn + r) * (size_t)kdim + kc2) + (arr & 1) * 128;
                    soff = (arr & 1) ? OFF_WP1 : OFF_W;
                }
                const uint32_t dst = st2 + soff;
                cp16(dst + swz(r, cc),     gp + cc * 16);
                cp16(dst + swz(r, cc + 4), gp + (cc + 4) * 16);
            }

            // fragment prefetch
            if (s < 7) {
                const int s1 = s + 1;
                const uint32_t ap = st + ((s1 >> 2) ? OFF_AP1 : 0);
                const uint32_t wp = st + ((s1 >> 2) ? OFF_WP1 : OFF_W);
                const int c0 = 2 * (s1 & 3);
                #pragma unroll
                for (int mt = 0; mt < 4; mt++)
                    ldsm_x4(af[nxt][mt], ap + swz(a_row + mt * 16, c0 + a_chi));
                #pragma unroll
                for (int np = 0; np < 2; np++)
                    ldsm_x4(bf[nxt][np], wp + swz(b_row + np * 16, c0 + b_chi));
            } else if (more) {
                // cross-chunk prefetch: next chunk's s0 from stage k+1
                #pragma unroll
                for (int mt = 0; mt < 4; mt++)
                    ldsm_x4(af[nxt][mt], stn + swz(a_row + mt * 16, a_chi));
                #pragma unroll
                for (int np = 0; np < 2; np++)
                    ldsm_x4(bf[nxt][np], stn + OFF_W + swz(b_row + np * 16, b_chi));
            }

            #pragma unroll
            for (int mt = 0; mt < 4; mt++)
                #pragma unroll
                for (int nt = 0; nt < 4; nt++)
                    mma_f16(acc[mt][nt], af[cur][mt], bf[cur][nt >> 1] + (nt & 1) * 2);

            if (s == 6 && more) {
                cp_wait<0>();
                __syncthreads();
            }
        }
        cp_commit();
    }

    // epilogue (acc carries W*4096 scale)
    const int er = bm + warp_m * 64 + (lane >> 2);
    const int ec = bn + warp_n * 32 + (lane & 3) * 2;

    #pragma unroll
    for (int mt = 0; mt < 4; mt++) {
        #pragma unroll
        for (int half = 0; half < 2; half++) {
            const size_t row = (size_t)(er + mt * 16 + half * 8) * HH;
            #pragma unroll
            for (int nt = 0; nt < 4; nt++) {
                const int n = ec + nt * 8;
                const float* a2 = &acc[mt][nt][half * 2];
                if (!GATE) {
                    float2 v = { tanhf(a2[0] * INV_WSCALE), tanhf(a2[1] * INV_WSCALE) };
                    *(float2*)(&out0[row + n]) = v;
                } else {
                    float2 bi = *(const float2*)(&bias[n]);
                    float2 sv = *(const float2*)(&state[row + n]);
                    float2 vv = *(const float2*)(&values_in[row + n]);
                    float2 pg = { a2[0] * INV_WSCALE + bi.x, a2[1] * INV_WSCALE + bi.y };
                    float2 g  = { fminf(fmaxf(pg.x, 0.f), 1.f), fminf(fmaxf(pg.y, 0.f), 1.f) };
                    float2 ph = { sv.x * (1.f - g.x) + vv.x * g.x,
                                  sv.y * (1.f - g.y) + vv.y * g.y };
                    float2 nh = { fmaxf(ph.x, 0.f), fmaxf(ph.y, 0.f) };
                    *(float2*)(&out0[row + n])    = pg;
                    *(float2*)(&gate_o[row + n])  = g;
                    *(float2*)(&pre_h_o[row + n]) = ph;
                    *(float2*)(&new_h_o[row + n]) = nh;
                }
            }
        }
    }

    // ride-along Wg convert (values kernel only): this CTA's 1/1024 slice.
    // Wg total = HH*KG = 8M fp32 = 2M float4; 2048 float4 per CTA, 8 per thread.
    if (!GATE) {
        const int tile_id = blockIdx.y * gridDim.x + blockIdx.x;   // 0..1023
        const float4* src = wgsrc + (size_t)tile_id * 2048;
        __half2* dst = wgdst + (size_t)tile_id * 4096;
        #pragma unroll
        for (int j = 0; j < 8; j++) {
            const int i = t + j * 256;
            float4 v = src[i];
            dst[i * 2 + 0] = __floats2half2_rn(v.x * WSCALE, v.y * WSCALE);
            dst[i * 2 + 1] = __floats2half2_rn(v.z * WSCALE, v.w * WSCALE);
        }
    }
}

// ---------------- launch ----------------
extern "C" void kernel_launch(void* const* d_in, const int* in_sizes, int n_in,
                              void* d_out, int out_size) {
    const float* input  = (const float*)d_in[0];
    const float* state  = (const float*)d_in[1];
    const float* gate_w = (const float*)d_in[2];
    const float* gate_b = (const float*)d_in[3];
    const float* w_i    = (const float*)d_in[4];

    float* out = (float*)d_out;
    float* new_h    = out;
    float* concat   = new_h + (size_t)Bb * HH;
    float* pre_gate = concat + (size_t)Bb * KG;
    float* gate     = pre_gate + (size_t)Bb * HH;
    float* values   = gate + (size_t)Bb * HH;
    float* pre_h    = values + (size_t)Bb * HH;

    void *cah, *wgh, *wih;
    cudaGetSymbolAddress(&cah, g_CAh);
    cudaGetSymbolAddress(&wgh, g_Wgh);
    cudaGetSymbolAddress(&wih, g_Wih);

    cudaFuncSetAttribute(gemm_mma<false>, cudaFuncAttributeMaxDynamicSharedMemorySize, SMEM_TOTAL);
    cudaFuncSetAttribute(gemm_mma<true>,  cudaFuncAttributeMaxDynamicSharedMemorySize, SMEM_TOTAL);

    // merged convert: A(+concat) 16384 blocks | Wi 4096 blocks
    convert_all<<<16384 + 4096, 256>>>(
        (const float4*)input, (const float4*)state, (float4*)concat,
        (const float4*)w_i);

    dim3 grid(HH / BN, Bb / BM);  // (16, 64)
    // values GEMM + ride-along Wg conversion
    gemm_mma<false><<<grid, NTH, SMEM_TOTAL>>>(
        (const __half*)cah, (const __half*)wih, INN,
        nullptr, nullptr, nullptr, values, nullptr, nullptr, nullptr,
        (const float4*)gate_w, (__half2*)wgh);

    // gate GEMM (Wg fp16 ready after values kernel completes)
    gemm_mma<true><<<grid, NTH, SMEM_TOTAL>>>(
        (const __half*)cah, (const __half*)wgh, KG,
        state, gate_b, values, pre_gate, gate, pre_h, new_h,
        nullptr, nullptr);
}